// round 14
// baseline (speedup 1.0000x reference)
#include <cuda_runtime.h>
#include <cuda_bf16.h>
#include <mma.h>
#include <cstdint>

using namespace nvcuda;
using bf16 = __nv_bfloat16;

// ---------------- problem dims --------------------------------------------------
constexpr int B_  = 2;
constexpr int N_  = 2048;
constexpr int D_  = 1024;
constexpr int H_  = 8;
constexpr int DK_ = 128;
constexpr int DV_ = 1024;
constexpr int HDK = H_ * DK_;    // 1024
constexpr int HDV = H_ * DV_;    // 8192
constexpr int HN  = H_ * N_;     // 16384
constexpr int NSPLIT = 4;        // AV head-splits (2 heads each)

// ---------------- tiling / smem config -------------------------------------------
constexpr int A_STRIDE = 40;              // K-major stage row stride (elems), BK=32
constexpr int EP_STRIDE = 136;            // fp32 epilogue stage stride

// NT kernels (128x128, BK=32): A 128x40 + B 128x40 per stage
constexpr int STAGE_BYTES = 20480;
constexpr int DSMEM = 4 * STAGE_BYTES;    // 81920 (>= 128x136 fp32 epilogue stage)

// ---------------- scratch (__device__ globals) ----------------------------------
__device__ bf16 g_xb [(size_t)B_ * N_ * D_];
__device__ bf16 g_wqb[(size_t)H_ * DK_ * D_];
__device__ bf16 g_wkb[(size_t)H_ * DK_ * D_];
__device__ bf16 g_wvb[(size_t)H_ * DV_ * D_];
__device__ bf16 g_Q  [(size_t)B_ * N_ * HDK];
__device__ bf16 g_K  [(size_t)B_ * N_ * HDK];
__device__ bf16 g_Vt [(size_t)B_ * HDV * N_];                 // [B][H*DV][N]
__device__ bf16 g_sim[(size_t)B_ * N_ * HN];                  // lower-tri tiles only
__device__ float g_part[(size_t)NSPLIT * B_ * N_ * DV_];      // 64 MB AV partials

// ---------------- fragment types -------------------------------------------------
using FragA  = wmma::fragment<wmma::matrix_a, 16, 16, 16, bf16, wmma::row_major>;
using FragBc = wmma::fragment<wmma::matrix_b, 16, 16, 16, bf16, wmma::col_major>;
using FragC  = wmma::fragment<wmma::accumulator, 16, 16, 16, float>;

// ---------------- cp.async helpers -----------------------------------------------
__device__ __forceinline__ uint32_t smem_u32(const void* p) {
    uint32_t a;
    asm("{ .reg .u64 t; cvta.to.shared.u64 t, %1; cvt.u32.u64 %0, t; }"
        : "=r"(a) : "l"(p));
    return a;
}
__device__ __forceinline__ void cp16(uint32_t dst, const void* src) {
    asm volatile("cp.async.cg.shared.global [%0], [%1], 16;"
                 :: "r"(dst), "l"(__cvta_generic_to_global(src)));
}
__device__ __forceinline__ void cp_commit() {
    asm volatile("cp.async.commit_group;" ::: "memory");
}
__device__ __forceinline__ void cp_wait2() {
    asm volatile("cp.async.wait_group 2;" ::: "memory");
}

// 128 rows x 32 cols K-major (row stride 40 elems), 128 threads, 4 cp16 each
__device__ __forceinline__ void ld_A(uint32_t sdst, const bf16* g, int ld, int tid) {
#pragma unroll
    for (int i = 0; i < 4; ++i) {
        int u = tid + i * 128;
        int r = u >> 2, c = (u & 3) * 8;
        cp16(sdst + (uint32_t)(r * (A_STRIDE * 2) + c * 2), g + (size_t)r * ld + c);
    }
}

// ---------------- MMA micro-step: warp tile 64x64, NT -----------------------------
__device__ __forceinline__ void mma_w64(FragC acc[4][4], const bf16* As, const bf16* Bs,
                                        int wm, int wn) {
#pragma unroll
    for (int ks = 0; ks < 32; ks += 16) {
        FragA a[4];
#pragma unroll
        for (int i = 0; i < 4; ++i)
            wmma::load_matrix_sync(a[i], As + (wm * 64 + i * 16) * A_STRIDE + ks, A_STRIDE);
#pragma unroll
        for (int j = 0; j < 4; ++j) {
            FragBc b;
            wmma::load_matrix_sync(b, Bs + (wn * 64 + j * 16) * A_STRIDE + ks, A_STRIDE);
#pragma unroll
            for (int i = 0; i < 4; ++i)
                wmma::mma_sync(acc[i][j], a[i], b, acc[i][j]);
        }
    }
}

// ---------------- pipelined NT mainloop (128x128, 128 threads) ---------------------
__device__ __forceinline__ void loop_nt(FragC acc[4][4], char* dsm,
                                        const bf16* A, int lda,
                                        const bf16* Bp, int ldb,
                                        int nk, int tid, int wm, int wn) {
    uint32_t sb = smem_u32(dsm);
#pragma unroll
    for (int s = 0; s < 3; ++s) {
        if (s < nk) {
            ld_A(sb + s * STAGE_BYTES,         A  + s * 32, lda, tid);
            ld_A(sb + s * STAGE_BYTES + 10240, Bp + s * 32, ldb, tid);
        }
        cp_commit();
    }
    for (int i = 0; i < nk; ++i) {
        cp_wait2();
        __syncthreads();
        int ci = i + 3;
        if (ci < nk) {
            uint32_t st = sb + (uint32_t)(ci & 3) * STAGE_BYTES;
            ld_A(st,         A  + ci * 32, lda, tid);
            ld_A(st + 10240, Bp + ci * 32, ldb, tid);
        }
        cp_commit();
        const bf16* As = reinterpret_cast<const bf16*>(dsm + (i & 3) * STAGE_BYTES);
        mma_w64(acc, As, As + 10240 / 2, wm, wn);
    }
    __syncthreads();
}

// ---------------- epilogues (128 threads) ------------------------------------------
__device__ __forceinline__ void stage_acc16(FragC acc[4][4], float* stg, int wm, int wn) {
#pragma unroll
    for (int i = 0; i < 4; ++i)
#pragma unroll
        for (int j = 0; j < 4; ++j)
            wmma::store_matrix_sync(stg + (wm * 64 + i * 16) * EP_STRIDE + wn * 64 + j * 16,
                                    acc[i][j], EP_STRIDE, wmma::mem_row_major);
}

// MODE 0: plain bf16. MODE 1: causal relu/N bf16.
template <int MODE>
__device__ __forceinline__ void ep_bf16(FragC acc[4][4], char* dsm, bf16* C, int ldc,
                                        int q0, int m0, int tid, int wm, int wn) {
    float* stg = reinterpret_cast<float*>(dsm);
    stage_acc16(acc, stg, wm, wn);
    __syncthreads();
    const float inv_n = 1.0f / (float)N_;
#pragma unroll
    for (int it = 0; it < 16; ++it) {
        int idx = it * 128 + tid;
        int r = idx >> 4, cv = idx & 15;
        const float* p = stg + r * EP_STRIDE + cv * 8;
        union { bf16 v[8]; uint4 u4; } pk;
#pragma unroll
        for (int e = 0; e < 8; ++e) {
            float v = p[e];
            if (MODE == 1) {
                int gm = m0 + cv * 8 + e;
                v = (gm <= q0 + r) ? fmaxf(v, 0.0f) * inv_n : 0.0f;
            }
            pk.v[e] = __float2bfloat16(v);
        }
        *reinterpret_cast<uint4*>(C + (size_t)r * ldc + cv * 8) = pk.u4;
    }
    __syncthreads();
}

// ---------------- kernels ---------------------------------------------------------
// merged fp32->bf16 conversion of all four tensors (prefix-range partition)
__global__ void conv_all_kernel(const float4* __restrict__ sx,
                                const float4* __restrict__ sq,
                                const float4* __restrict__ sk,
                                const float4* __restrict__ sv,
                                __nv_bfloat162* __restrict__ dx,
                                __nv_bfloat162* __restrict__ dq,
                                __nv_bfloat162* __restrict__ dk,
                                __nv_bfloat162* __restrict__ dv) {
    constexpr int N_X = (B_ * N_ * D_) / 4;
    constexpr int N_Q = (H_ * DK_ * D_) / 4;
    constexpr int N_V = (H_ * DV_ * D_) / 4;
    constexpr int T1 = N_X, T2 = T1 + N_Q, T3 = T2 + N_Q, T4 = T3 + N_V;

    int i = blockIdx.x * blockDim.x + threadIdx.x;
    if (i >= T4) return;
    const float4* src; __nv_bfloat162* dst; int j;
    if (i < T1)      { src = sx; dst = dx; j = i; }
    else if (i < T2) { src = sq; dst = dq; j = i - T1; }
    else if (i < T3) { src = sk; dst = dk; j = i - T2; }
    else             { src = sv; dst = dv; j = i - T3; }
    float4 v = src[j];
    dst[2 * j]     = __floats2bfloat162_rn(v.x, v.y);
    dst[2 * j + 1] = __floats2bfloat162_rn(v.z, v.w);
}

// merged projections: bx<8 -> Q, bx<16 -> K, bx>=16 -> Vt (Wv x^T)
__global__ __launch_bounds__(128) void k_qkv(const bf16* __restrict__ xb,
                                             const bf16* __restrict__ wq,
                                             const bf16* __restrict__ wk,
                                             const bf16* __restrict__ wv,
                                             bf16* __restrict__ Q,
                                             bf16* __restrict__ K,
                                             bf16* __restrict__ Vt) {
    extern __shared__ char dsm[];
    int tid = threadIdx.x, wid = tid >> 5;
    int wm = wid & 1, wn = wid >> 1;

    int bx = blockIdx.x, by = blockIdx.y;
    const bf16 *A, *Bp;
    bf16* C;
    int ldc;
    if (bx < 8) {
        A  = xb + (size_t)by * 128 * D_;
        Bp = wq + (size_t)bx * 128 * D_;
        C  = Q + (size_t)(by * 128) * HDK + bx * 128;
        ldc = HDK;
    } else if (bx < 16) {
        A  = xb + (size_t)by * 128 * D_;
        Bp = wk + (size_t)(bx - 8) * 128 * D_;
        C  = K + (size_t)(by * 128) * HDK + (bx - 8) * 128;
        ldc = HDK;
    } else {
        // Vt[b] = Wv * x[b]^T : A = Wv row-tile, B = x row-tile
        int vidx = (bx - 16) * 32 + by;    // 0..2047
        int wt = vidx >> 5;                // Wv row tile 0..63
        int r  = vidx & 31;
        int b  = r >> 4;                   // batch
        int nt = r & 15;                   // n tile
        A  = wv + (size_t)wt * 128 * D_;
        Bp = xb + ((size_t)(b * N_ + nt * 128)) * D_;
        C  = Vt + ((size_t)b * HDV + wt * 128) * N_ + nt * 128;
        ldc = N_;
    }

    FragC acc[4][4];
#pragma unroll
    for (int i = 0; i < 4; ++i)
#pragma unroll
        for (int j = 0; j < 4; ++j) wmma::fill_fragment(acc[i][j], 0.0f);

    loop_nt(acc, dsm, A, D_, Bp, D_, D_ / 32, tid, wm, wn);
    ep_bf16<0>(acc, dsm, C, ldc, 0, 0, tid, wm, wn);
}

__global__ __launch_bounds__(128) void k_scores(const bf16* __restrict__ Q,
                                                const bf16* __restrict__ Kx,
                                                bf16* __restrict__ sim) {
    int mt = blockIdx.x, nt = blockIdx.y;
    if (mt > nt) return;                       // upper tiles never read by AV
    int b = blockIdx.z >> 3, h = blockIdx.z & 7;
    extern __shared__ char dsm[];
    int tid = threadIdx.x, wid = tid >> 5;
    int wm = wid & 1, wn = wid >> 1;

    const bf16* A  = Q  + ((size_t)(b * N_ + nt * 128)) * HDK + h * DK_;
    const bf16* Bp = Kx + ((size_t)(b * N_ + mt * 128)) * HDK + h * DK_;
    bf16* C = sim + ((size_t)(b * N_ + nt * 128)) * HN + (size_t)h * N_ + mt * 128;

    FragC acc[4][4];
#pragma unroll
    for (int i = 0; i < 4; ++i)
#pragma unroll
        for (int j = 0; j < 4; ++j) wmma::fill_fragment(acc[i][j], 0.0f);

    loop_nt(acc, dsm, A, HDK, Bp, HDK, DK_ / 32, tid, wm, wn);
    ep_bf16<1>(acc, dsm, C, HN, nt * 128, mt * 128, tid, wm, wn);
}

// AV split-K partials, NT form: block = 128-row sim tile x 128 Vt rows x 2 heads.
// Both operands K-major (stride-40 stages), mma_w64. Critical path <= 128 chunks.
__global__ __launch_bounds__(128) void k_avp(const bf16* __restrict__ sim,
                                             const bf16* __restrict__ Vt,
                                             float* __restrict__ part) {
    int vt = blockIdx.x;
    int tn = 15 - blockIdx.y;            // heavy tiles first
    int z = blockIdx.z;
    int b = z >> 2, s = z & 3;           // split s covers heads {2s, 2s+1}

    extern __shared__ char dsm[];
    uint32_t sb = smem_u32(dsm);
    int tid = threadIdx.x, wid = tid >> 5;
    int wm = wid & 1, wn = wid >> 1;     // warp tile 64x64 over 128x128 output

    const bf16* Arow = sim + ((size_t)(b * N_ + tn * 128)) * HN;       // + h*N + kc*32
    const bf16* Bvt  = Vt + ((size_t)b * HDV + vt * 128) * N_;         // + h*DV*N + kc*32

    const int nkh = (tn + 1) * 4;        // K=32 chunks per head (causal bound), >= 4
    const int nk  = nkh * 2;             // two heads; >= 8

    FragC acc[4][4];
#pragma unroll
    for (int i = 0; i < 4; ++i)
#pragma unroll
        for (int j = 0; j < 4; ++j) wmma::fill_fragment(acc[i][j], 0.0f);

#pragma unroll
    for (int sg = 0; sg < 3; ++sg) {     // prologue chunks all in head 2s (nkh >= 4)
        int h = 2 * s;
        ld_A(sb + sg * STAGE_BYTES,         Arow + h * N_ + sg * 32, HN, tid);
        ld_A(sb + sg * STAGE_BYTES + 10240, Bvt + (size_t)h * DV_ * N_ + sg * 32, N_, tid);
        cp_commit();
    }
    for (int i = 0; i < nk; ++i) {
        cp_wait2();
        __syncthreads();
        int ci = i + 3;
        if (ci < nk) {
            int h = 2 * s + ci / nkh, kc = ci % nkh;
            uint32_t st = sb + (uint32_t)(ci & 3) * STAGE_BYTES;
            ld_A(st,         Arow + h * N_ + kc * 32, HN, tid);
            ld_A(st + 10240, Bvt + (size_t)h * DV_ * N_ + kc * 32, N_, tid);
        }
        cp_commit();
        const bf16* As = reinterpret_cast<const bf16*>(dsm + (i & 3) * STAGE_BYTES);
        mma_w64(acc, As, As + 10240 / 2, wm, wn);
    }
    __syncthreads();

    // epilogue: stage 128x136 fp32, plain float4 stores to partial buffer
    float* stg = reinterpret_cast<float*>(dsm);
    stage_acc16(acc, stg, wm, wn);
    __syncthreads();
    float* pb = part + (size_t)s * (B_ * N_ * DV_);
    size_t rowbase = (size_t)(b * N_ + tn * 128);
#pragma unroll
    for (int it = 0; it < 32; ++it) {
        int idx = it * 128 + tid;
        int r = idx >> 5, cv = idx & 31;
        size_t o = (rowbase + r) * (size_t)DV_ + vt * 128 + cv * 4;
        const float* p = stg + r * EP_STRIDE + cv * 4;
        *reinterpret_cast<float4*>(pb + o) = make_float4(p[0], p[1], p[2], p[3]);
    }
}

// final reduce: out = x + sum of 4 partials
__global__ void k_reduce(const float4* __restrict__ x,
                         const float4* __restrict__ part,
                         float4* __restrict__ out) {
    constexpr int NT4 = (B_ * N_ * DV_) / 4;   // 1048576
    int i = blockIdx.x * blockDim.x + threadIdx.x;
    if (i >= NT4) return;
    float4 v = x[i];
#pragma unroll
    for (int s = 0; s < NSPLIT; ++s) {
        float4 p = part[(size_t)s * NT4 + i];
        v.x += p.x; v.y += p.y; v.z += p.z; v.w += p.w;
    }
    out[i] = v;
}

// ---------------- host launcher ---------------------------------------------------
extern "C" void kernel_launch(void* const* d_in, const int* in_sizes, int n_in,
                              void* d_out, int out_size) {
    (void)in_sizes; (void)n_in; (void)out_size;
    const float* x  = (const float*)d_in[0];
    const float* Wq = (const float*)d_in[1];
    const float* Wk = (const float*)d_in[2];
    const float* Wv = (const float*)d_in[3];

    bf16 *xb, *wqb, *wkb, *wvb, *Q, *K, *Vt, *sim;
    float* part;
    cudaGetSymbolAddress((void**)&xb,  g_xb);
    cudaGetSymbolAddress((void**)&wqb, g_wqb);
    cudaGetSymbolAddress((void**)&wkb, g_wkb);
    cudaGetSymbolAddress((void**)&wvb, g_wvb);
    cudaGetSymbolAddress((void**)&Q,   g_Q);
    cudaGetSymbolAddress((void**)&K,   g_K);
    cudaGetSymbolAddress((void**)&Vt,  g_Vt);
    cudaGetSymbolAddress((void**)&sim, g_sim);
    cudaGetSymbolAddress((void**)&part, g_part);

    cudaFuncSetAttribute(k_qkv,    cudaFuncAttributeMaxDynamicSharedMemorySize, DSMEM);
    cudaFuncSetAttribute(k_scores, cudaFuncAttributeMaxDynamicSharedMemorySize, DSMEM);
    cudaFuncSetAttribute(k_avp,    cudaFuncAttributeMaxDynamicSharedMemorySize, DSMEM);

    // one conversion launch for x, Wq, Wk, Wv
    constexpr int TOT4 = (B_ * N_ * D_ + 2 * H_ * DK_ * D_ + H_ * DV_ * D_) / 4;
    conv_all_kernel<<<(TOT4 + 255) / 256, 256>>>(
        reinterpret_cast<const float4*>(x),
        reinterpret_cast<const float4*>(Wq),
        reinterpret_cast<const float4*>(Wk),
        reinterpret_cast<const float4*>(Wv),
        reinterpret_cast<__nv_bfloat162*>(xb),
        reinterpret_cast<__nv_bfloat162*>(wqb),
        reinterpret_cast<__nv_bfloat162*>(wkb),
        reinterpret_cast<__nv_bfloat162*>(wvb));

    // one merged projection launch: Q, K, Vt  (2560 blocks)
    k_qkv<<<dim3(80, 32), 128, DSMEM>>>(xb, wqb, wkb, wvb, Q, K, Vt);

    // sim = causal relu(Q K^T)/N  (lower-triangle tiles only)
    k_scores<<<dim3(16, 16, 16), 128, DSMEM>>>(Q, K, sim);

    // AV partials: 8 vt x 16 tn x (2 b x 4 splits) = 1024 blocks, heavy-first
    k_avp<<<dim3(8, 16, 8), 128, DSMEM>>>(sim, Vt, part);

    // out = x + sum partials
    constexpr int NT4 = (B_ * N_ * DV_) / 4;
    k_reduce<<<(NT4 + 255) / 256, 256>>>(
        reinterpret_cast<const float4*>(x),
        reinterpret_cast<const float4*>(part),
        reinterpret_cast<float4*>(d_out));
}

// round 15
// speedup vs baseline: 1.0534x; 1.0534x over previous
#include <cuda_runtime.h>
#include <cuda_bf16.h>
#include <mma.h>
#include <cstdint>

using namespace nvcuda;
using bf16 = __nv_bfloat16;

// ---------------- problem dims --------------------------------------------------
constexpr int B_  = 2;
constexpr int N_  = 2048;
constexpr int D_  = 1024;
constexpr int H_  = 8;
constexpr int DK_ = 128;
constexpr int DV_ = 1024;
constexpr int HDK = H_ * DK_;    // 1024
constexpr int HDV = H_ * DV_;    // 8192
constexpr int HN  = H_ * N_;     // 16384
constexpr int NSPLIT = 4;        // AV head-splits (2 heads each)

// ---------------- tiling / smem config -------------------------------------------
constexpr int A_STRIDE = 40;              // K-major stage row stride (elems), BK=32
constexpr int B_ROW_STRIDE = 136;         // row-major B stage row stride (elems)
constexpr int EP_STRIDE = 136;            // fp32 epilogue stage stride

// NT kernels (128x128, BK=32): A 128x40 + B 128x40 per stage
constexpr int STAGE_BYTES = 20480;
constexpr int DSMEM = 4 * STAGE_BYTES;    // 81920 (>= 128x136 fp32 epilogue stage)

// AV (128x128, BK=32): A 128x40 (10240B) + B 32x136 (8704B)
constexpr int AVP_A_BYTES = 128 * A_STRIDE * 2;                  // 10240
constexpr int AVP_STAGE   = AVP_A_BYTES + 32 * B_ROW_STRIDE * 2; // 18944
constexpr int AVP_DSMEM   = 4 * AVP_STAGE;                       // 75776 (>= 69632 ep)

// ---------------- scratch (__device__ globals) ----------------------------------
__device__ bf16 g_xb [(size_t)B_ * N_ * D_];
__device__ bf16 g_wqb[(size_t)H_ * DK_ * D_];
__device__ bf16 g_wkb[(size_t)H_ * DK_ * D_];
__device__ bf16 g_wvb[(size_t)H_ * DV_ * D_];
__device__ bf16 g_Q  [(size_t)B_ * N_ * HDK];
__device__ bf16 g_K  [(size_t)B_ * N_ * HDK];
__device__ bf16 g_V  [(size_t)B_ * H_ * N_ * DV_];            // [B][H][N][DV]
__device__ bf16 g_sim[(size_t)B_ * H_ * N_ * N_];             // [B][H][N][N] lower-tri
__device__ float g_part[(size_t)NSPLIT * B_ * N_ * DV_];      // 64 MB AV partials

// ---------------- fragment types -------------------------------------------------
using FragA  = wmma::fragment<wmma::matrix_a, 16, 16, 16, bf16, wmma::row_major>;
using FragBc = wmma::fragment<wmma::matrix_b, 16, 16, 16, bf16, wmma::col_major>;
using FragBr = wmma::fragment<wmma::matrix_b, 16, 16, 16, bf16, wmma::row_major>;
using FragC  = wmma::fragment<wmma::accumulator, 16, 16, 16, float>;

// ---------------- cp.async helpers -----------------------------------------------
__device__ __forceinline__ uint32_t smem_u32(const void* p) {
    uint32_t a;
    asm("{ .reg .u64 t; cvta.to.shared.u64 t, %1; cvt.u32.u64 %0, t; }"
        : "=r"(a) : "l"(p));
    return a;
}
__device__ __forceinline__ void cp16(uint32_t dst, const void* src) {
    asm volatile("cp.async.cg.shared.global [%0], [%1], 16;"
                 :: "r"(dst), "l"(__cvta_generic_to_global(src)));
}
__device__ __forceinline__ void cp_commit() {
    asm volatile("cp.async.commit_group;" ::: "memory");
}
__device__ __forceinline__ void cp_wait2() {
    asm volatile("cp.async.wait_group 2;" ::: "memory");
}

// 128 rows x 32 cols K-major (row stride 40 elems), 128 threads, 4 cp16 each
__device__ __forceinline__ void ld_A(uint32_t sdst, const bf16* g, int ld, int tid) {
#pragma unroll
    for (int i = 0; i < 4; ++i) {
        int u = tid + i * 128;
        int r = u >> 2, c = (u & 3) * 8;
        cp16(sdst + (uint32_t)(r * (A_STRIDE * 2) + c * 2), g + (size_t)r * ld + c);
    }
}
// 32 rows(k) x 128 cols(n) row-major (row stride 136 elems), 128 threads
__device__ __forceinline__ void ld_Brow(uint32_t sdst, const bf16* g, int ld, int tid) {
#pragma unroll
    for (int i = 0; i < 4; ++i) {
        int u = tid + i * 128;
        int r = u >> 4, c = (u & 15) * 8;
        cp16(sdst + (uint32_t)(r * (B_ROW_STRIDE * 2) + c * 2), g + (size_t)r * ld + c);
    }
}

// ---------------- MMA micro-steps --------------------------------------------------
// warp tile 64x64, NT (B col-major view, stride 40)
__device__ __forceinline__ void mma_w64(FragC acc[4][4], const bf16* As, const bf16* Bs,
                                        int wm, int wn) {
#pragma unroll
    for (int ks = 0; ks < 32; ks += 16) {
        FragA a[4];
#pragma unroll
        for (int i = 0; i < 4; ++i)
            wmma::load_matrix_sync(a[i], As + (wm * 64 + i * 16) * A_STRIDE + ks, A_STRIDE);
#pragma unroll
        for (int j = 0; j < 4; ++j) {
            FragBc b;
            wmma::load_matrix_sync(b, Bs + (wn * 64 + j * 16) * A_STRIDE + ks, A_STRIDE);
#pragma unroll
            for (int i = 0; i < 4; ++i)
                wmma::mma_sync(acc[i][j], a[i], b, acc[i][j]);
        }
    }
}
// warp tile 64x64, B row-major (stride 136) — AV
__device__ __forceinline__ void mma_w64r(FragC acc[4][4], const bf16* As, const bf16* Bs,
                                         int wm, int wn) {
#pragma unroll
    for (int ks = 0; ks < 32; ks += 16) {
        FragA a[4];
#pragma unroll
        for (int i = 0; i < 4; ++i)
            wmma::load_matrix_sync(a[i], As + (wm * 64 + i * 16) * A_STRIDE + ks, A_STRIDE);
#pragma unroll
        for (int j = 0; j < 4; ++j) {
            FragBr b;
            wmma::load_matrix_sync(b, Bs + ks * B_ROW_STRIDE + wn * 64 + j * 16, B_ROW_STRIDE);
#pragma unroll
            for (int i = 0; i < 4; ++i)
                wmma::mma_sync(acc[i][j], a[i], b, acc[i][j]);
        }
    }
}

// ---------------- pipelined NT mainloop (128x128, 128 threads) ---------------------
__device__ __forceinline__ void loop_nt(FragC acc[4][4], char* dsm,
                                        const bf16* A, int lda,
                                        const bf16* Bp, int ldb,
                                        int nk, int tid, int wm, int wn) {
    uint32_t sb = smem_u32(dsm);
#pragma unroll
    for (int s = 0; s < 3; ++s) {
        if (s < nk) {
            ld_A(sb + s * STAGE_BYTES,         A  + s * 32, lda, tid);
            ld_A(sb + s * STAGE_BYTES + 10240, Bp + s * 32, ldb, tid);
        }
        cp_commit();
    }
    for (int i = 0; i < nk; ++i) {
        cp_wait2();
        __syncthreads();
        int ci = i + 3;
        if (ci < nk) {
            uint32_t st = sb + (uint32_t)(ci & 3) * STAGE_BYTES;
            ld_A(st,         A  + ci * 32, lda, tid);
            ld_A(st + 10240, Bp + ci * 32, ldb, tid);
        }
        cp_commit();
        const bf16* As = reinterpret_cast<const bf16*>(dsm + (i & 3) * STAGE_BYTES);
        mma_w64(acc, As, As + 10240 / 2, wm, wn);
    }
    __syncthreads();
}

// ---------------- epilogues (128 threads) ------------------------------------------
__device__ __forceinline__ void stage_acc16(FragC acc[4][4], float* stg, int wm, int wn) {
#pragma unroll
    for (int i = 0; i < 4; ++i)
#pragma unroll
        for (int j = 0; j < 4; ++j)
            wmma::store_matrix_sync(stg + (wm * 64 + i * 16) * EP_STRIDE + wn * 64 + j * 16,
                                    acc[i][j], EP_STRIDE, wmma::mem_row_major);
}

// MODE 0: plain bf16. MODE 1: causal relu/N bf16.
template <int MODE>
__device__ __forceinline__ void ep_bf16(FragC acc[4][4], char* dsm, bf16* C, int ldc,
                                        int q0, int m0, int tid, int wm, int wn) {
    float* stg = reinterpret_cast<float*>(dsm);
    stage_acc16(acc, stg, wm, wn);
    __syncthreads();
    const float inv_n = 1.0f / (float)N_;
#pragma unroll
    for (int it = 0; it < 16; ++it) {
        int idx = it * 128 + tid;
        int r = idx >> 4, cv = idx & 15;
        const float* p = stg + r * EP_STRIDE + cv * 8;
        union { bf16 v[8]; uint4 u4; } pk;
#pragma unroll
        for (int e = 0; e < 8; ++e) {
            float v = p[e];
            if (MODE == 1) {
                int gm = m0 + cv * 8 + e;
                v = (gm <= q0 + r) ? fmaxf(v, 0.0f) * inv_n : 0.0f;
            }
            pk.v[e] = __float2bfloat16(v);
        }
        *reinterpret_cast<uint4*>(C + (size_t)r * ldc + cv * 8) = pk.u4;
    }
    __syncthreads();
}

// ---------------- kernels ---------------------------------------------------------
// merged fp32->bf16 conversion of all four tensors (prefix-range partition)
__global__ void conv_all_kernel(const float4* __restrict__ sx,
                                const float4* __restrict__ sq,
                                const float4* __restrict__ sk,
                                const float4* __restrict__ sv,
                                __nv_bfloat162* __restrict__ dx,
                                __nv_bfloat162* __restrict__ dq,
                                __nv_bfloat162* __restrict__ dk,
                                __nv_bfloat162* __restrict__ dv) {
    constexpr int N_X = (B_ * N_ * D_) / 4;
    constexpr int N_Q = (H_ * DK_ * D_) / 4;
    constexpr int N_V = (H_ * DV_ * D_) / 4;
    constexpr int T1 = N_X, T2 = T1 + N_Q, T3 = T2 + N_Q, T4 = T3 + N_V;

    int i = blockIdx.x * blockDim.x + threadIdx.x;
    if (i >= T4) return;
    const float4* src; __nv_bfloat162* dst; int j;
    if (i < T1)      { src = sx; dst = dx; j = i; }
    else if (i < T2) { src = sq; dst = dq; j = i - T1; }
    else if (i < T3) { src = sk; dst = dk; j = i - T2; }
    else             { src = sv; dst = dv; j = i - T3; }
    float4 v = src[j];
    dst[2 * j]     = __floats2bfloat162_rn(v.x, v.y);
    dst[2 * j + 1] = __floats2bfloat162_rn(v.z, v.w);
}

// merged Q/K/V projection: bx in [0,8)->Q, [8,16)->K, [16,80)->V (per-head layout)
__global__ __launch_bounds__(128) void k_qkv(const bf16* __restrict__ xb,
                                             const bf16* __restrict__ wq,
                                             const bf16* __restrict__ wk,
                                             const bf16* __restrict__ wv,
                                             bf16* __restrict__ Q,
                                             bf16* __restrict__ K,
                                             bf16* __restrict__ V) {
    extern __shared__ char dsm[];
    int tid = threadIdx.x, wid = tid >> 5;
    int wm = wid & 1, wn = wid >> 1;

    int bx = blockIdx.x, by = blockIdx.y;
    const bf16* W; bf16* C; int ldc;
    const bf16* A = xb + (size_t)by * 128 * D_;
    const bf16* Bp;
    if (bx < 8) {
        Bp = wq + (size_t)bx * 128 * D_;
        C  = Q + (size_t)(by * 128) * HDK + bx * 128;
        ldc = HDK;
    } else if (bx < 16) {
        Bp = wk + (size_t)(bx - 8) * 128 * D_;
        C  = K + (size_t)(by * 128) * HDK + (bx - 8) * 128;
        ldc = HDK;
    } else {
        int xt = bx - 16;                  // 0..63 over HDV
        int h = xt >> 3, dvc = xt & 7;     // head, dv-chunk
        int b = by >> 4, nt = by & 15;     // batch, n-tile
        Bp = wv + (size_t)xt * 128 * D_;
        C  = V + (((size_t)(b * H_ + h)) * N_ + nt * 128) * DV_ + dvc * 128;
        ldc = DV_;
    }

    FragC acc[4][4];
#pragma unroll
    for (int i = 0; i < 4; ++i)
#pragma unroll
        for (int j = 0; j < 4; ++j) wmma::fill_fragment(acc[i][j], 0.0f);

    loop_nt(acc, dsm, A, D_, Bp, D_, D_ / 32, tid, wm, wn);
    ep_bf16<0>(acc, dsm, C, ldc, 0, 0, tid, wm, wn);
}

__global__ __launch_bounds__(128) void k_scores(const bf16* __restrict__ Q,
                                                const bf16* __restrict__ Kx,
                                                bf16* __restrict__ sim) {
    int mt = blockIdx.x, nt = blockIdx.y;
    if (mt > nt) return;                       // upper tiles never read by AV
    int b = blockIdx.z >> 3, h = blockIdx.z & 7;
    extern __shared__ char dsm[];
    int tid = threadIdx.x, wid = tid >> 5;
    int wm = wid & 1, wn = wid >> 1;

    const bf16* A  = Q  + ((size_t)(b * N_ + nt * 128)) * HDK + h * DK_;
    const bf16* Bp = Kx + ((size_t)(b * N_ + mt * 128)) * HDK + h * DK_;
    // per-head sim layout [B][H][N][N]
    bf16* C = sim + (((size_t)(b * H_ + h)) * N_ + nt * 128) * N_ + mt * 128;

    FragC acc[4][4];
#pragma unroll
    for (int i = 0; i < 4; ++i)
#pragma unroll
        for (int j = 0; j < 4; ++j) wmma::fill_fragment(acc[i][j], 0.0f);

    loop_nt(acc, dsm, A, HDK, Bp, HDK, DK_ / 32, tid, wm, wn);
    ep_bf16<1>(acc, dsm, C, N_, nt * 128, mt * 128, tid, wm, wn);
}

// AV split-K partials, per-head layouts: block = 128-row sim tile x 128 V-cols
// x 2 heads. A ld = N_ (4KB), B ld = DV_ (2KB). Critical path <= 128 chunks.
__global__ __launch_bounds__(128) void k_avp(const bf16* __restrict__ sim,
                                             const bf16* __restrict__ V,
                                             float* __restrict__ part) {
    int vt = blockIdx.x;
    int tn = 15 - blockIdx.y;            // heavy tiles first
    int z = blockIdx.z;
    int b = z >> 2, s = z & 3;           // split s covers heads {2s, 2s+1}

    extern __shared__ char dsm[];
    uint32_t sb = smem_u32(dsm);
    int tid = threadIdx.x, wid = tid >> 5;
    int wm = wid & 1, wn = wid >> 1;     // warp tile 64x64 over 128x128 output

    // per-head base pointers (head 2s and 2s+1)
    const bf16* A0 = sim + (((size_t)(b * H_ + 2 * s)) * N_ + tn * 128) * N_;
    const bf16* A1 = A0 + (size_t)N_ * N_;
    const bf16* V0 = V + ((size_t)(b * H_ + 2 * s)) * N_ * DV_ + vt * 128;
    const bf16* V1 = V0 + (size_t)N_ * DV_;

    const int nkh = (tn + 1) * 4;        // K=32 chunks per head (causal bound), >= 4
    const int nk  = nkh * 2;             // two heads; >= 8

    FragC acc[4][4];
#pragma unroll
    for (int i = 0; i < 4; ++i)
#pragma unroll
        for (int j = 0; j < 4; ++j) wmma::fill_fragment(acc[i][j], 0.0f);

#pragma unroll
    for (int sg = 0; sg < 3; ++sg) {     // prologue chunks all in head 2s (nkh >= 4)
        ld_A   (sb + sg * AVP_STAGE, A0 + sg * 32, N_, tid);
        ld_Brow(sb + sg * AVP_STAGE + AVP_A_BYTES,
                V0 + (size_t)(sg * 32) * DV_, DV_, tid);
        cp_commit();
    }
    for (int i = 0; i < nk; ++i) {
        cp_wait2();
        __syncthreads();
        int ci = i + 3;
        if (ci < nk) {
            int hl = ci / nkh, kc = ci % nkh;
            const bf16* Ah = hl ? A1 : A0;
            const bf16* Vh = hl ? V1 : V0;
            uint32_t st = sb + (uint32_t)(ci & 3) * AVP_STAGE;
            ld_A   (st, Ah + kc * 32, N_, tid);
            ld_Brow(st + AVP_A_BYTES, Vh + (size_t)(kc * 32) * DV_, DV_, tid);
        }
        cp_commit();
        const bf16* As = reinterpret_cast<const bf16*>(dsm + (i & 3) * AVP_STAGE);
        mma_w64r(acc, As, As + AVP_A_BYTES / 2, wm, wn);
    }
    __syncthreads();

    // epilogue: stage 128x136 fp32, plain float4 stores to partial buffer
    float* stg = reinterpret_cast<float*>(dsm);
    stage_acc16(acc, stg, wm, wn);
    __syncthreads();
    float* pb = part + (size_t)s * (B_ * N_ * DV_);
    size_t rowbase = (size_t)(b * N_ + tn * 128);
#pragma unroll
    for (int it = 0; it < 32; ++it) {
        int idx = it * 128 + tid;
        int r = idx >> 5, cv = idx & 31;
        size_t o = (rowbase + r) * (size_t)DV_ + vt * 128 + cv * 4;
        const float* p = stg + r * EP_STRIDE + cv * 4;
        *reinterpret_cast<float4*>(pb + o) = make_float4(p[0], p[1], p[2], p[3]);
    }
}

// final reduce: out = x + sum of 4 partials
__global__ void k_reduce(const float4* __restrict__ x,
                         const float4* __restrict__ part,
                         float4* __restrict__ out) {
    constexpr int NT4 = (B_ * N_ * DV_) / 4;   // 1048576
    int i = blockIdx.x * blockDim.x + threadIdx.x;
    if (i >= NT4) return;
    float4 v = x[i];
#pragma unroll
    for (int s = 0; s < NSPLIT; ++s) {
        float4 p = part[(size_t)s * NT4 + i];
        v.x += p.x; v.y += p.y; v.z += p.z; v.w += p.w;
    }
    out[i] = v;
}

// ---------------- host launcher ---------------------------------------------------
extern "C" void kernel_launch(void* const* d_in, const int* in_sizes, int n_in,
                              void* d_out, int out_size) {
    (void)in_sizes; (void)n_in; (void)out_size;
    const float* x  = (const float*)d_in[0];
    const float* Wq = (const float*)d_in[1];
    const float* Wk = (const float*)d_in[2];
    const float* Wv = (const float*)d_in[3];

    bf16 *xb, *wqb, *wkb, *wvb, *Q, *K, *V, *sim;
    float* part;
    cudaGetSymbolAddress((void**)&xb,  g_xb);
    cudaGetSymbolAddress((void**)&wqb, g_wqb);
    cudaGetSymbolAddress((void**)&wkb, g_wkb);
    cudaGetSymbolAddress((void**)&wvb, g_wvb);
    cudaGetSymbolAddress((void**)&Q,   g_Q);
    cudaGetSymbolAddress((void**)&K,   g_K);
    cudaGetSymbolAddress((void**)&V,   g_V);
    cudaGetSymbolAddress((void**)&sim, g_sim);
    cudaGetSymbolAddress((void**)&part, g_part);

    cudaFuncSetAttribute(k_qkv,    cudaFuncAttributeMaxDynamicSharedMemorySize, DSMEM);
    cudaFuncSetAttribute(k_scores, cudaFuncAttributeMaxDynamicSharedMemorySize, DSMEM);
    cudaFuncSetAttribute(k_avp,    cudaFuncAttributeMaxDynamicSharedMemorySize, AVP_DSMEM);

    // one conversion launch for x, Wq, Wk, Wv
    constexpr int TOT4 = (B_ * N_ * D_ + 2 * H_ * DK_ * D_ + H_ * DV_ * D_) / 4;
    conv_all_kernel<<<(TOT4 + 255) / 256, 256>>>(
        reinterpret_cast<const float4*>(x),
        reinterpret_cast<const float4*>(Wq),
        reinterpret_cast<const float4*>(Wk),
        reinterpret_cast<const float4*>(Wv),
        reinterpret_cast<__nv_bfloat162*>(xb),
        reinterpret_cast<__nv_bfloat162*>(wqb),
        reinterpret_cast<__nv_bfloat162*>(wkb),
        reinterpret_cast<__nv_bfloat162*>(wvb));

    // one merged projection launch: Q, K, V  (2560 blocks)
    k_qkv<<<dim3(80, (B_ * N_) / 128), 128, DSMEM>>>(xb, wqb, wkb, wvb, Q, K, V);

    // sim = causal relu(Q K^T)/N  (lower-triangle tiles only, per-head layout)
    k_scores<<<dim3(16, 16, 16), 128, DSMEM>>>(Q, K, sim);

    // AV partials: 8 vt x 16 tn x (2 b x 4 splits) = 1024 blocks, heavy-first
    k_avp<<<dim3(8, 16, 8), 128, AVP_DSMEM>>>(sim, V, part);

    // out = x + sum partials
    constexpr int NT4 = (B_ * N_ * DV_) / 4;
    k_reduce<<<(NT4 + 255) / 256, 256>>>(
        reinterpret_cast<const float4*>(x),
        reinterpret_cast<const float4*>(part),
        reinterpret_cast<float4*>(d_out));
}

// round 16
// speedup vs baseline: 1.0934x; 1.0380x over previous
#include <cuda_runtime.h>
#include <cuda_bf16.h>
#include <mma.h>
#include <cstdint>

using namespace nvcuda;
using bf16 = __nv_bfloat16;

// ---------------- problem dims --------------------------------------------------
constexpr int B_  = 2;
constexpr int N_  = 2048;
constexpr int D_  = 1024;
constexpr int H_  = 8;
constexpr int DK_ = 128;
constexpr int DV_ = 1024;
constexpr int HDK = H_ * DK_;    // 1024
constexpr int HDV = H_ * DV_;    // 8192
constexpr int NSPLIT = 4;        // AV head-splits (2 heads each)

// ---------------- tiling / smem config -------------------------------------------
constexpr int A_STRIDE = 40;              // K-major stage row stride, BK=32 kernels
constexpr int AV_ASTRIDE = 72;            // K-major stage row stride, BK=64 (AV)
constexpr int B_ROW_STRIDE = 136;         // row-major B stage row stride (elems)
constexpr int EP_STRIDE = 136;            // fp32 epilogue stage stride

// NT kernels (128x128, BK=32): A 128x40 + B 128x40 per stage
constexpr int STAGE_BYTES = 20480;
constexpr int DSMEM = 4 * STAGE_BYTES;    // 81920 (>= 128x136 fp32 epilogue stage)

// AV (128x128, BK=64): A 128x72 (18432B) + B 64x136 (17408B)
constexpr int AVP_A_BYTES = 128 * AV_ASTRIDE * 2;                // 18432
constexpr int AVP_STAGE   = AVP_A_BYTES + 64 * B_ROW_STRIDE * 2; // 35840
constexpr int AVP_DSMEM   = 3 * AVP_STAGE;                       // 107520 (>= 69632 ep)

// ---------------- scratch (__device__ globals) ----------------------------------
__device__ bf16 g_xb [(size_t)B_ * N_ * D_];
__device__ bf16 g_wqb[(size_t)H_ * DK_ * D_];
__device__ bf16 g_wkb[(size_t)H_ * DK_ * D_];
__device__ bf16 g_wvb[(size_t)H_ * DV_ * D_];
__device__ bf16 g_Q  [(size_t)B_ * N_ * HDK];
__device__ bf16 g_K  [(size_t)B_ * N_ * HDK];
__device__ bf16 g_V  [(size_t)B_ * H_ * N_ * DV_];            // [B][H][N][DV]
__device__ bf16 g_sim[(size_t)B_ * H_ * N_ * N_];             // [B][H][N][N] lower-tri
__device__ float g_part[(size_t)NSPLIT * B_ * N_ * DV_];      // 64 MB AV partials

// ---------------- fragment types -------------------------------------------------
using FragA  = wmma::fragment<wmma::matrix_a, 16, 16, 16, bf16, wmma::row_major>;
using FragBc = wmma::fragment<wmma::matrix_b, 16, 16, 16, bf16, wmma::col_major>;
using FragBr = wmma::fragment<wmma::matrix_b, 16, 16, 16, bf16, wmma::row_major>;
using FragC  = wmma::fragment<wmma::accumulator, 16, 16, 16, float>;

// ---------------- cp.async helpers -----------------------------------------------
__device__ __forceinline__ uint32_t smem_u32(const void* p) {
    uint32_t a;
    asm("{ .reg .u64 t; cvta.to.shared.u64 t, %1; cvt.u32.u64 %0, t; }"
        : "=r"(a) : "l"(p));
    return a;
}
__device__ __forceinline__ void cp16(uint32_t dst, const void* src) {
    asm volatile("cp.async.cg.shared.global [%0], [%1], 16;"
                 :: "r"(dst), "l"(__cvta_generic_to_global(src)));
}
__device__ __forceinline__ void cp_commit() {
    asm volatile("cp.async.commit_group;" ::: "memory");
}
__device__ __forceinline__ void cp_wait2() {
    asm volatile("cp.async.wait_group 2;" ::: "memory");
}
__device__ __forceinline__ void cp_wait1() {
    asm volatile("cp.async.wait_group 1;" ::: "memory");
}

// 128 rows x 32 cols K-major (row stride 40 elems), 128 threads, 4 cp16 each
__device__ __forceinline__ void ld_A(uint32_t sdst, const bf16* g, int ld, int tid) {
#pragma unroll
    for (int i = 0; i < 4; ++i) {
        int u = tid + i * 128;
        int r = u >> 2, c = (u & 3) * 8;
        cp16(sdst + (uint32_t)(r * (A_STRIDE * 2) + c * 2), g + (size_t)r * ld + c);
    }
}
// 128 rows x 64 cols K-major (row stride 72 elems), 128 threads, 8 cp16 each
__device__ __forceinline__ void ld_A72(uint32_t sdst, const bf16* g, int ld, int tid) {
#pragma unroll
    for (int i = 0; i < 8; ++i) {
        int u = tid + i * 128;
        int r = u >> 3, c8 = u & 7;
        cp16(sdst + (uint32_t)(r * (AV_ASTRIDE * 2) + c8 * 16), g + (size_t)r * ld + c8 * 8);
    }
}
// 64 rows(k) x 128 cols(n) row-major (row stride 136 elems), 128 threads, 8 cp16 each
__device__ __forceinline__ void ld_Brow64(uint32_t sdst, const bf16* g, int ld, int tid) {
#pragma unroll
    for (int i = 0; i < 8; ++i) {
        int u = tid + i * 128;
        int r = u >> 4, c16 = u & 15;
        cp16(sdst + (uint32_t)(r * (B_ROW_STRIDE * 2) + c16 * 16), g + (size_t)r * ld + c16 * 8);
    }
}

// ---------------- MMA micro-steps --------------------------------------------------
// warp tile 64x64, NT (B col-major view, stride 40), BK=32
__device__ __forceinline__ void mma_w64(FragC acc[4][4], const bf16* As, const bf16* Bs,
                                        int wm, int wn) {
#pragma unroll
    for (int ks = 0; ks < 32; ks += 16) {
        FragA a[4];
#pragma unroll
        for (int i = 0; i < 4; ++i)
            wmma::load_matrix_sync(a[i], As + (wm * 64 + i * 16) * A_STRIDE + ks, A_STRIDE);
#pragma unroll
        for (int j = 0; j < 4; ++j) {
            FragBc b;
            wmma::load_matrix_sync(b, Bs + (wn * 64 + j * 16) * A_STRIDE + ks, A_STRIDE);
#pragma unroll
            for (int i = 0; i < 4; ++i)
                wmma::mma_sync(acc[i][j], a[i], b, acc[i][j]);
        }
    }
}
// warp tile 64x64, B row-major (stride 136), BK=64 — AV
__device__ __forceinline__ void mma_w64r64(FragC acc[4][4], const bf16* As, const bf16* Bs,
                                           int wm, int wn) {
#pragma unroll
    for (int ks = 0; ks < 64; ks += 16) {
        FragA a[4];
#pragma unroll
        for (int i = 0; i < 4; ++i)
            wmma::load_matrix_sync(a[i], As + (wm * 64 + i * 16) * AV_ASTRIDE + ks, AV_ASTRIDE);
#pragma unroll
        for (int j = 0; j < 4; ++j) {
            FragBr b;
            wmma::load_matrix_sync(b, Bs + ks * B_ROW_STRIDE + wn * 64 + j * 16, B_ROW_STRIDE);
#pragma unroll
            for (int i = 0; i < 4; ++i)
                wmma::mma_sync(acc[i][j], a[i], b, acc[i][j]);
        }
    }
}

// ---------------- pipelined NT mainloop (128x128, BK=32, 128 threads) --------------
__device__ __forceinline__ void loop_nt(FragC acc[4][4], char* dsm,
                                        const bf16* A, int lda,
                                        const bf16* Bp, int ldb,
                                        int nk, int tid, int wm, int wn) {
    uint32_t sb = smem_u32(dsm);
#pragma unroll
    for (int s = 0; s < 3; ++s) {
        if (s < nk) {
            ld_A(sb + s * STAGE_BYTES,         A  + s * 32, lda, tid);
            ld_A(sb + s * STAGE_BYTES + 10240, Bp + s * 32, ldb, tid);
        }
        cp_commit();
    }
    for (int i = 0; i < nk; ++i) {
        cp_wait2();
        __syncthreads();
        int ci = i + 3;
        if (ci < nk) {
            uint32_t st = sb + (uint32_t)(ci & 3) * STAGE_BYTES;
            ld_A(st,         A  + ci * 32, lda, tid);
            ld_A(st + 10240, Bp + ci * 32, ldb, tid);
        }
        cp_commit();
        const bf16* As = reinterpret_cast<const bf16*>(dsm + (i & 3) * STAGE_BYTES);
        mma_w64(acc, As, As + 10240 / 2, wm, wn);
    }
    __syncthreads();
}

// ---------------- epilogues (128 threads) ------------------------------------------
__device__ __forceinline__ void stage_acc16(FragC acc[4][4], float* stg, int wm, int wn) {
#pragma unroll
    for (int i = 0; i < 4; ++i)
#pragma unroll
        for (int j = 0; j < 4; ++j)
            wmma::store_matrix_sync(stg + (wm * 64 + i * 16) * EP_STRIDE + wn * 64 + j * 16,
                                    acc[i][j], EP_STRIDE, wmma::mem_row_major);
}

// MODE 0: plain bf16. MODE 1: causal relu/N bf16.
template <int MODE>
__device__ __forceinline__ void ep_bf16(FragC acc[4][4], char* dsm, bf16* C, int ldc,
                                        int q0, int m0, int tid, int wm, int wn) {
    float* stg = reinterpret_cast<float*>(dsm);
    stage_acc16(acc, stg, wm, wn);
    __syncthreads();
    const float inv_n = 1.0f / (float)N_;
#pragma unroll
    for (int it = 0; it < 16; ++it) {
        int idx = it * 128 + tid;
        int r = idx >> 4, cv = idx & 15;
        const float* p = stg + r * EP_STRIDE + cv * 8;
        union { bf16 v[8]; uint4 u4; } pk;
#pragma unroll
        for (int e = 0; e < 8; ++e) {
            float v = p[e];
            if (MODE == 1) {
                int gm = m0 + cv * 8 + e;
                v = (gm <= q0 + r) ? fmaxf(v, 0.0f) * inv_n : 0.0f;
            }
            pk.v[e] = __float2bfloat16(v);
        }
        *reinterpret_cast<uint4*>(C + (size_t)r * ldc + cv * 8) = pk.u4;
    }
    __syncthreads();
}

// ---------------- kernels ---------------------------------------------------------
// merged fp32->bf16 conversion of all four tensors (prefix-range partition)
__global__ void conv_all_kernel(const float4* __restrict__ sx,
                                const float4* __restrict__ sq,
                                const float4* __restrict__ sk,
                                const float4* __restrict__ sv,
                                __nv_bfloat162* __restrict__ dx,
                                __nv_bfloat162* __restrict__ dq,
                                __nv_bfloat162* __restrict__ dk,
                                __nv_bfloat162* __restrict__ dv) {
    constexpr int N_X = (B_ * N_ * D_) / 4;
    constexpr int N_Q = (H_ * DK_ * D_) / 4;
    constexpr int N_V = (H_ * DV_ * D_) / 4;
    constexpr int T1 = N_X, T2 = T1 + N_Q, T3 = T2 + N_Q, T4 = T3 + N_V;

    int i = blockIdx.x * blockDim.x + threadIdx.x;
    if (i >= T4) return;
    const float4* src; __nv_bfloat162* dst; int j;
    if (i < T1)      { src = sx; dst = dx; j = i; }
    else if (i < T2) { src = sq; dst = dq; j = i - T1; }
    else if (i < T3) { src = sk; dst = dk; j = i - T2; }
    else             { src = sv; dst = dv; j = i - T3; }
    float4 v = src[j];
    dst[2 * j]     = __floats2bfloat162_rn(v.x, v.y);
    dst[2 * j + 1] = __floats2bfloat162_rn(v.z, v.w);
}

// merged Q/K/V projection: bx in [0,8)->Q, [8,16)->K, [16,80)->V (per-head layout)
__global__ __launch_bounds__(128) void k_qkv(const bf16* __restrict__ xb,
                                             const bf16* __restrict__ wq,
                                             const bf16* __restrict__ wk,
                                             const bf16* __restrict__ wv,
                                             bf16* __restrict__ Q,
                                             bf16* __restrict__ K,
                                             bf16* __restrict__ V) {
    extern __shared__ char dsm[];
    int tid = threadIdx.x, wid = tid >> 5;
    int wm = wid & 1, wn = wid >> 1;

    int bx = blockIdx.x, by = blockIdx.y;
    bf16* C; int ldc;
    const bf16* A = xb + (size_t)by * 128 * D_;
    const bf16* Bp;
    if (bx < 8) {
        Bp = wq + (size_t)bx * 128 * D_;
        C  = Q + (size_t)(by * 128) * HDK + bx * 128;
        ldc = HDK;
    } else if (bx < 16) {
        Bp = wk + (size_t)(bx - 8) * 128 * D_;
        C  = K + (size_t)(by * 128) * HDK + (bx - 8) * 128;
        ldc = HDK;
    } else {
        int xt = bx - 16;                  // 0..63 over HDV
        int h = xt >> 3, dvc = xt & 7;     // head, dv-chunk
        int b = by >> 4, nt = by & 15;     // batch, n-tile
        Bp = wv + (size_t)xt * 128 * D_;
        C  = V + (((size_t)(b * H_ + h)) * N_ + nt * 128) * DV_ + dvc * 128;
        ldc = DV_;
    }

    FragC acc[4][4];
#pragma unroll
    for (int i = 0; i < 4; ++i)
#pragma unroll
        for (int j = 0; j < 4; ++j) wmma::fill_fragment(acc[i][j], 0.0f);

    loop_nt(acc, dsm, A, D_, Bp, D_, D_ / 32, tid, wm, wn);
    ep_bf16<0>(acc, dsm, C, ldc, 0, 0, tid, wm, wn);
}

__global__ __launch_bounds__(128) void k_scores(const bf16* __restrict__ Q,
                                                const bf16* __restrict__ Kx,
                                                bf16* __restrict__ sim) {
    int mt = blockIdx.x, nt = blockIdx.y;
    if (mt > nt) return;                       // upper tiles never read by AV
    int b = blockIdx.z >> 3, h = blockIdx.z & 7;
    extern __shared__ char dsm[];
    int tid = threadIdx.x, wid = tid >> 5;
    int wm = wid & 1, wn = wid >> 1;

    const bf16* A  = Q  + ((size_t)(b * N_ + nt * 128)) * HDK + h * DK_;
    const bf16* Bp = Kx + ((size_t)(b * N_ + mt * 128)) * HDK + h * DK_;
    bf16* C = sim + (((size_t)(b * H_ + h)) * N_ + nt * 128) * N_ + mt * 128;

    FragC acc[4][4];
#pragma unroll
    for (int i = 0; i < 4; ++i)
#pragma unroll
        for (int j = 0; j < 4; ++j) wmma::fill_fragment(acc[i][j], 0.0f);

    loop_nt(acc, dsm, A, HDK, Bp, HDK, DK_ / 32, tid, wm, wn);
    ep_bf16<1>(acc, dsm, C, N_, nt * 128, mt * 128, tid, wm, wn);
}

// AV split-K partials, BK=64: block = 128-row sim tile x 128 V-cols x 2 heads.
// 3-stage ring (prologue 2, wait 1). A ld = N_, B ld = DV_ (per-head layouts).
__global__ __launch_bounds__(128) void k_avp(const bf16* __restrict__ sim,
                                             const bf16* __restrict__ V,
                                             float* __restrict__ part) {
    int vt = blockIdx.x;
    int tn = 15 - blockIdx.y;            // heavy tiles first
    int z = blockIdx.z;
    int b = z >> 2, s = z & 3;           // split s covers heads {2s, 2s+1}

    extern __shared__ char dsm[];
    uint32_t sb = smem_u32(dsm);
    int tid = threadIdx.x, wid = tid >> 5;
    int wm = wid & 1, wn = wid >> 1;     // warp tile 64x64 over 128x128 output

    // per-head base pointers (head 2s and 2s+1)
    const bf16* A0 = sim + (((size_t)(b * H_ + 2 * s)) * N_ + tn * 128) * N_;
    const bf16* A1 = A0 + (size_t)N_ * N_;
    const bf16* V0 = V + ((size_t)(b * H_ + 2 * s)) * N_ * DV_ + vt * 128;
    const bf16* V1 = V0 + (size_t)N_ * DV_;

    const int nkh = (tn + 1) * 2;        // K=64 chunks per head (causal bound), >= 2
    const int nk  = nkh * 2;             // two heads; >= 4

    FragC acc[4][4];
#pragma unroll
    for (int i = 0; i < 4; ++i)
#pragma unroll
        for (int j = 0; j < 4; ++j) wmma::fill_fragment(acc[i][j], 0.0f);

#pragma unroll
    for (int sg = 0; sg < 2; ++sg) {     // prologue chunks all in head 2s (nkh >= 2)
        ld_A72   (sb + sg * AVP_STAGE, A0 + sg * 64, N_, tid);
        ld_Brow64(sb + sg * AVP_STAGE + AVP_A_BYTES,
                  V0 + (size_t)(sg * 64) * DV_, DV_, tid);
        cp_commit();
    }
    for (int i = 0; i < nk; ++i) {
        cp_wait1();
        __syncthreads();
        int ci = i + 2;
        if (ci < nk) {
            int hl = ci / nkh, kc = ci % nkh;
            const bf16* Ah = hl ? A1 : A0;
            const bf16* Vh = hl ? V1 : V0;
            uint32_t st = sb + (uint32_t)(ci % 3) * AVP_STAGE;
            ld_A72   (st, Ah + kc * 64, N_, tid);
            ld_Brow64(st + AVP_A_BYTES, Vh + (size_t)(kc * 64) * DV_, DV_, tid);
        }
        cp_commit();
        const bf16* As = reinterpret_cast<const bf16*>(dsm + (i % 3) * AVP_STAGE);
        mma_w64r64(acc, As, As + AVP_A_BYTES / 2, wm, wn);
    }
    __syncthreads();

    // epilogue: stage 128x136 fp32, plain float4 stores to partial buffer
    float* stg = reinterpret_cast<float*>(dsm);
    stage_acc16(acc, stg, wm, wn);
    __syncthreads();
    float* pb = part + (size_t)s * (B_ * N_ * DV_);
    size_t rowbase = (size_t)(b * N_ + tn * 128);
#pragma unroll
    for (int it = 0; it < 32; ++it) {
        int idx = it * 128 + tid;
        int r = idx >> 5, cv = idx & 31;
        size_t o = (rowbase + r) * (size_t)DV_ + vt * 128 + cv * 4;
        const float* p = stg + r * EP_STRIDE + cv * 4;
        *reinterpret_cast<float4*>(pb + o) = make_float4(p[0], p[1], p[2], p[3]);
    }
}

// final reduce: out = x + sum of 4 partials
__global__ void k_reduce(const float4* __restrict__ x,
                         const float4* __restrict__ part,
                         float4* __restrict__ out) {
    constexpr int NT4 = (B_ * N_ * DV_) / 4;   // 1048576
    int i = blockIdx.x * blockDim.x + threadIdx.x;
    if (i >= NT4) return;
    float4 v = x[i];
#pragma unroll
    for (int s = 0; s < NSPLIT; ++s) {
        float4 p = part[(size_t)s * NT4 + i];
        v.x += p.x; v.y += p.y; v.z += p.z; v.w += p.w;
    }
    out[i] = v;
}

// ---------------- host launcher ---------------------------------------------------
extern "C" void kernel_launch(void* const* d_in, const int* in_sizes, int n_in,
                              void* d_out, int out_size) {
    (void)in_sizes; (void)n_in; (void)out_size;
    const float* x  = (const float*)d_in[0];
    const float* Wq = (const float*)d_in[1];
    const float* Wk = (const float*)d_in[2];
    const float* Wv = (const float*)d_in[3];

    bf16 *xb, *wqb, *wkb, *wvb, *Q, *K, *V, *sim;
    float* part;
    cudaGetSymbolAddress((void**)&xb,  g_xb);
    cudaGetSymbolAddress((void**)&wqb, g_wqb);
    cudaGetSymbolAddress((void**)&wkb, g_wkb);
    cudaGetSymbolAddress((void**)&wvb, g_wvb);
    cudaGetSymbolAddress((void**)&Q,   g_Q);
    cudaGetSymbolAddress((void**)&K,   g_K);
    cudaGetSymbolAddress((void**)&V,   g_V);
    cudaGetSymbolAddress((void**)&sim, g_sim);
    cudaGetSymbolAddress((void**)&part, g_part);

    cudaFuncSetAttribute(k_qkv,    cudaFuncAttributeMaxDynamicSharedMemorySize, DSMEM);
    cudaFuncSetAttribute(k_scores, cudaFuncAttributeMaxDynamicSharedMemorySize, DSMEM);
    cudaFuncSetAttribute(k_avp,    cudaFuncAttributeMaxDynamicSharedMemorySize, AVP_DSMEM);

    // one conversion launch for x, Wq, Wk, Wv
    constexpr int TOT4 = (B_ * N_ * D_ + 2 * H_ * DK_ * D_ + H_ * DV_ * D_) / 4;
    conv_all_kernel<<<(TOT4 + 255) / 256, 256>>>(
        reinterpret_cast<const float4*>(x),
        reinterpret_cast<const float4*>(Wq),
        reinterpret_cast<const float4*>(Wk),
        reinterpret_cast<const float4*>(Wv),
        reinterpret_cast<__nv_bfloat162*>(xb),
        reinterpret_cast<__nv_bfloat162*>(wqb),
        reinterpret_cast<__nv_bfloat162*>(wkb),
        reinterpret_cast<__nv_bfloat162*>(wvb));

    // one merged projection launch: Q, K, V  (2560 blocks)
    k_qkv<<<dim3(80, (B_ * N_) / 128), 128, DSMEM>>>(xb, wqb, wkb, wvb, Q, K, V);

    // sim = causal relu(Q K^T)/N  (lower-triangle tiles only, per-head layout)
    k_scores<<<dim3(16, 16, 16), 128, DSMEM>>>(Q, K, sim);

    // AV partials: 8 vt x 16 tn x (2 b x 4 splits) = 1024 blocks, heavy-first, BK=64
    k_avp<<<dim3(8, 16, 8), 128, AVP_DSMEM>>>(sim, V, part);

    // out = x + sum partials
    constexpr int NT4 = (B_ * N_ * DV_) / 4;
    k_reduce<<<(NT4 + 255) / 256, 256>>>(
        reinterpret_cast<const float4*>(x),
        reinterpret_cast<const float4*>(part),
        reinterpret_cast<float4*>(d_out));
}

// round 17
// speedup vs baseline: 1.1029x; 1.0087x over previous
#include <cuda_runtime.h>
#include <cuda_bf16.h>
#include <mma.h>
#include <cstdint>

using namespace nvcuda;
using bf16 = __nv_bfloat16;

// ---------------- problem dims --------------------------------------------------
constexpr int B_  = 2;
constexpr int N_  = 2048;
constexpr int D_  = 1024;
constexpr int H_  = 8;
constexpr int DK_ = 128;
constexpr int DV_ = 1024;
constexpr int HDK = H_ * DK_;    // 1024
constexpr int HDV = H_ * DV_;    // 8192
constexpr int NSPLIT = 4;        // AV head-splits (2 heads each)

// ---------------- tiling / smem config -------------------------------------------
constexpr int A_STRIDE = 40;              // K-major stage row stride, BK=32 kernels
constexpr int AV_ASTRIDE = 72;            // K-major stage row stride, BK=64 (AV)
constexpr int B_ROW_STRIDE = 136;         // row-major B stage row stride (elems)
constexpr int EP_STRIDE = 136;            // fp32 epilogue stage stride

// NT kernels (128x128, BK=32): A 128x40 + B 128x40 per stage
constexpr int STAGE_BYTES = 20480;
constexpr int DSMEM = 4 * STAGE_BYTES;    // 81920 (>= 128x136 fp32 epilogue stage)

// AV (128x128, BK=64): A 128x72 (18432B) + B 64x136 (17408B)
constexpr int AVP_A_BYTES = 128 * AV_ASTRIDE * 2;                // 18432
constexpr int AVP_STAGE   = AVP_A_BYTES + 64 * B_ROW_STRIDE * 2; // 35840
constexpr int AVP_DSMEM   = 3 * AVP_STAGE;                       // 107520 (>= 69632 ep)

// ---------------- scratch (__device__ globals) ----------------------------------
__device__ bf16 g_xb [(size_t)B_ * N_ * D_];
__device__ bf16 g_wqb[(size_t)H_ * DK_ * D_];
__device__ bf16 g_wkb[(size_t)H_ * DK_ * D_];
__device__ bf16 g_wvb[(size_t)H_ * DV_ * D_];
__device__ bf16 g_Q  [(size_t)B_ * N_ * HDK];
__device__ bf16 g_K  [(size_t)B_ * N_ * HDK];
__device__ bf16 g_V  [(size_t)B_ * H_ * N_ * DV_];            // [B][H][N][DV]
__device__ bf16 g_sim[(size_t)B_ * H_ * N_ * N_];             // [B][H][N][N] lower-tri
__device__ float g_part[(size_t)NSPLIT * B_ * N_ * DV_];      // 64 MB AV partials

// ---------------- fragment types -------------------------------------------------
using FragA  = wmma::fragment<wmma::matrix_a, 16, 16, 16, bf16, wmma::row_major>;
using FragBc = wmma::fragment<wmma::matrix_b, 16, 16, 16, bf16, wmma::col_major>;
using FragBr = wmma::fragment<wmma::matrix_b, 16, 16, 16, bf16, wmma::row_major>;
using FragC  = wmma::fragment<wmma::accumulator, 16, 16, 16, float>;

// ---------------- cp.async helpers -----------------------------------------------
__device__ __forceinline__ uint32_t smem_u32(const void* p) {
    uint32_t a;
    asm("{ .reg .u64 t; cvta.to.shared.u64 t, %1; cvt.u32.u64 %0, t; }"
        : "=r"(a) : "l"(p));
    return a;
}
__device__ __forceinline__ void cp16(uint32_t dst, const void* src) {
    asm volatile("cp.async.cg.shared.global [%0], [%1], 16;"
                 :: "r"(dst), "l"(__cvta_generic_to_global(src)));
}
__device__ __forceinline__ void cp_commit() {
    asm volatile("cp.async.commit_group;" ::: "memory");
}
__device__ __forceinline__ void cp_wait2() {
    asm volatile("cp.async.wait_group 2;" ::: "memory");
}
__device__ __forceinline__ void cp_wait1() {
    asm volatile("cp.async.wait_group 1;" ::: "memory");
}

// 128 rows x 32 cols K-major (row stride 40 elems), 128 threads, 4 cp16 each
__device__ __forceinline__ void ld_A(uint32_t sdst, const bf16* g, int ld, int tid) {
#pragma unroll
    for (int i = 0; i < 4; ++i) {
        int u = tid + i * 128;
        int r = u >> 2, c = (u & 3) * 8;
        cp16(sdst + (uint32_t)(r * (A_STRIDE * 2) + c * 2), g + (size_t)r * ld + c);
    }
}
// 128 rows x 64 cols K-major (row stride 72 elems), 128 threads, 8 cp16 each
__device__ __forceinline__ void ld_A72(uint32_t sdst, const bf16* g, int ld, int tid) {
#pragma unroll
    for (int i = 0; i < 8; ++i) {
        int u = tid + i * 128;
        int r = u >> 3, c8 = u & 7;
        cp16(sdst + (uint32_t)(r * (AV_ASTRIDE * 2) + c8 * 16), g + (size_t)r * ld + c8 * 8);
    }
}
// 64 rows(k) x 128 cols(n) row-major (row stride 136 elems), 128 threads, 8 cp16 each
__device__ __forceinline__ void ld_Brow64(uint32_t sdst, const bf16* g, int ld, int tid) {
#pragma unroll
    for (int i = 0; i < 8; ++i) {
        int u = tid + i * 128;
        int r = u >> 4, c16 = u & 15;
        cp16(sdst + (uint32_t)(r * (B_ROW_STRIDE * 2) + c16 * 16), g + (size_t)r * ld + c16 * 8);
    }
}

// ---------------- MMA micro-steps --------------------------------------------------
// warp tile 64x64, NT (B col-major view, stride 40), BK=32
__device__ __forceinline__ void mma_w64(FragC acc[4][4], const bf16* As, const bf16* Bs,
                                        int wm, int wn) {
#pragma unroll
    for (int ks = 0; ks < 32; ks += 16) {
        FragA a[4];
#pragma unroll
        for (int i = 0; i < 4; ++i)
            wmma::load_matrix_sync(a[i], As + (wm * 64 + i * 16) * A_STRIDE + ks, A_STRIDE);
#pragma unroll
        for (int j = 0; j < 4; ++j) {
            FragBc b;
            wmma::load_matrix_sync(b, Bs + (wn * 64 + j * 16) * A_STRIDE + ks, A_STRIDE);
#pragma unroll
            for (int i = 0; i < 4; ++i)
                wmma::mma_sync(acc[i][j], a[i], b, acc[i][j]);
        }
    }
}
// warp tile 64x64, B row-major (stride 136), BK=64 — AV
__device__ __forceinline__ void mma_w64r64(FragC acc[4][4], const bf16* As, const bf16* Bs,
                                           int wm, int wn) {
#pragma unroll
    for (int ks = 0; ks < 64; ks += 16) {
        FragA a[4];
#pragma unroll
        for (int i = 0; i < 4; ++i)
            wmma::load_matrix_sync(a[i], As + (wm * 64 + i * 16) * AV_ASTRIDE + ks, AV_ASTRIDE);
#pragma unroll
        for (int j = 0; j < 4; ++j) {
            FragBr b;
            wmma::load_matrix_sync(b, Bs + ks * B_ROW_STRIDE + wn * 64 + j * 16, B_ROW_STRIDE);
#pragma unroll
            for (int i = 0; i < 4; ++i)
                wmma::mma_sync(acc[i][j], a[i], b, acc[i][j]);
        }
    }
}

// ---------------- pipelined NT mainloop (128x128, BK=32, 128 threads) --------------
__device__ __forceinline__ void loop_nt(FragC acc[4][4], char* dsm,
                                        const bf16* A, int lda,
                                        const bf16* Bp, int ldb,
                                        int nk, int tid, int wm, int wn) {
    uint32_t sb = smem_u32(dsm);
#pragma unroll
    for (int s = 0; s < 3; ++s) {
        if (s < nk) {
            ld_A(sb + s * STAGE_BYTES,         A  + s * 32, lda, tid);
            ld_A(sb + s * STAGE_BYTES + 10240, Bp + s * 32, ldb, tid);
        }
        cp_commit();
    }
    for (int i = 0; i < nk; ++i) {
        cp_wait2();
        __syncthreads();
        int ci = i + 3;
        if (ci < nk) {
            uint32_t st = sb + (uint32_t)(ci & 3) * STAGE_BYTES;
            ld_A(st,         A  + ci * 32, lda, tid);
            ld_A(st + 10240, Bp + ci * 32, ldb, tid);
        }
        cp_commit();
        const bf16* As = reinterpret_cast<const bf16*>(dsm + (i & 3) * STAGE_BYTES);
        mma_w64(acc, As, As + 10240 / 2, wm, wn);
    }
    __syncthreads();
}

// ---------------- epilogues (128 threads) ------------------------------------------
__device__ __forceinline__ void stage_acc16(FragC acc[4][4], float* stg, int wm, int wn) {
#pragma unroll
    for (int i = 0; i < 4; ++i)
#pragma unroll
        for (int j = 0; j < 4; ++j)
            wmma::store_matrix_sync(stg + (wm * 64 + i * 16) * EP_STRIDE + wn * 64 + j * 16,
                                    acc[i][j], EP_STRIDE, wmma::mem_row_major);
}

// MODE 0: plain bf16. MODE 1: causal relu/N bf16.
template <int MODE>
__device__ __forceinline__ void ep_bf16(FragC acc[4][4], char* dsm, bf16* C, int ldc,
                                        int q0, int m0, int tid, int wm, int wn) {
    float* stg = reinterpret_cast<float*>(dsm);
    stage_acc16(acc, stg, wm, wn);
    __syncthreads();
    const float inv_n = 1.0f / (float)N_;
#pragma unroll
    for (int it = 0; it < 16; ++it) {
        int idx = it * 128 + tid;
        int r = idx >> 4, cv = idx & 15;
        const float* p = stg + r * EP_STRIDE + cv * 8;
        union { bf16 v[8]; uint4 u4; } pk;
#pragma unroll
        for (int e = 0; e < 8; ++e) {
            float v = p[e];
            if (MODE == 1) {
                int gm = m0 + cv * 8 + e;
                v = (gm <= q0 + r) ? fmaxf(v, 0.0f) * inv_n : 0.0f;
            }
            pk.v[e] = __float2bfloat16(v);
        }
        *reinterpret_cast<uint4*>(C + (size_t)r * ldc + cv * 8) = pk.u4;
    }
    __syncthreads();
}

// ---------------- kernels ---------------------------------------------------------
// merged fp32->bf16 conversion of all four tensors (prefix-range partition)
__global__ void conv_all_kernel(const float4* __restrict__ sx,
                                const float4* __restrict__ sq,
                                const float4* __restrict__ sk,
                                const float4* __restrict__ sv,
                                __nv_bfloat162* __restrict__ dx,
                                __nv_bfloat162* __restrict__ dq,
                                __nv_bfloat162* __restrict__ dk,
                                __nv_bfloat162* __restrict__ dv) {
    constexpr int N_X = (B_ * N_ * D_) / 4;
    constexpr int N_Q = (H_ * DK_ * D_) / 4;
    constexpr int N_V = (H_ * DV_ * D_) / 4;
    constexpr int T1 = N_X, T2 = T1 + N_Q, T3 = T2 + N_Q, T4 = T3 + N_V;

    int i = blockIdx.x * blockDim.x + threadIdx.x;
    if (i >= T4) return;
    const float4* src; __nv_bfloat162* dst; int j;
    if (i < T1)      { src = sx; dst = dx; j = i; }
    else if (i < T2) { src = sq; dst = dq; j = i - T1; }
    else if (i < T3) { src = sk; dst = dk; j = i - T2; }
    else             { src = sv; dst = dv; j = i - T3; }
    float4 v = src[j];
    dst[2 * j]     = __floats2bfloat162_rn(v.x, v.y);
    dst[2 * j + 1] = __floats2bfloat162_rn(v.z, v.w);
}

// Q/K projections only: bx in [0,8)->Q, [8,16)->K  (512 blocks)
__global__ __launch_bounds__(128) void k_qk(const bf16* __restrict__ xb,
                                            const bf16* __restrict__ wq,
                                            const bf16* __restrict__ wk,
                                            bf16* __restrict__ Q,
                                            bf16* __restrict__ K) {
    extern __shared__ char dsm[];
    int tid = threadIdx.x, wid = tid >> 5;
    int wm = wid & 1, wn = wid >> 1;

    int bx = blockIdx.x, by = blockIdx.y;
    const bf16* A = xb + (size_t)by * 128 * D_;
    const bf16* Bp;
    bf16* C;
    if (bx < 8) {
        Bp = wq + (size_t)bx * 128 * D_;
        C  = Q + (size_t)(by * 128) * HDK + bx * 128;
    } else {
        Bp = wk + (size_t)(bx - 8) * 128 * D_;
        C  = K + (size_t)(by * 128) * HDK + (bx - 8) * 128;
    }

    FragC acc[4][4];
#pragma unroll
    for (int i = 0; i < 4; ++i)
#pragma unroll
        for (int j = 0; j < 4; ++j) wmma::fill_fragment(acc[i][j], 0.0f);

    loop_nt(acc, dsm, A, D_, Bp, D_, D_ / 32, tid, wm, wn);
    ep_bf16<0>(acc, dsm, C, HDK, 0, 0, tid, wm, wn);
}

// merged V-projection + scores (one launch; V blocks first, scores backfill tail)
//   bid <  2048 : V-proj block (nk = 32)
//   bid >= 2048 : scores block (nk = 4), lower-triangle (nt, mt) via triangular decode
__global__ __launch_bounds__(128) void k_sv(const bf16* __restrict__ xb,
                                            const bf16* __restrict__ wv,
                                            const bf16* __restrict__ Q,
                                            const bf16* __restrict__ Kx,
                                            bf16* __restrict__ V,
                                            bf16* __restrict__ sim) {
    extern __shared__ char dsm[];
    int tid = threadIdx.x, wid = tid >> 5;
    int wm = wid & 1, wn = wid >> 1;
    int bid = blockIdx.x;

    FragC acc[4][4];
#pragma unroll
    for (int i = 0; i < 4; ++i)
#pragma unroll
        for (int j = 0; j < 4; ++j) wmma::fill_fragment(acc[i][j], 0.0f);

    if (bid < 2048) {
        // V projection: per-head layout [B][H][N][DV]
        int xt = bid & 63;                 // Wv row tile (0..63)
        int by = bid >> 6;                 // x row tile (0..31)
        int h = xt >> 3, dvc = xt & 7;
        int b = by >> 4, nt = by & 15;
        const bf16* A  = xb + (size_t)by * 128 * D_;
        const bf16* Bp = wv + (size_t)xt * 128 * D_;
        bf16* C = V + (((size_t)(b * H_ + h)) * N_ + nt * 128) * DV_ + dvc * 128;

        loop_nt(acc, dsm, A, D_, Bp, D_, D_ / 32, tid, wm, wn);
        ep_bf16<0>(acc, dsm, C, DV_, 0, 0, tid, wm, wn);
    } else {
        // scores: lower-triangle tile p, batch-head bh
        int t = bid - 2048;                // 0..2175
        int bh = t & 15;
        int p  = t >> 4;                   // 0..135
        int nt = (int)((sqrtf(8.0f * (float)p + 1.0f) - 1.0f) * 0.5f);
        while ((nt + 1) * (nt + 2) / 2 <= p) ++nt;
        while (nt * (nt + 1) / 2 > p) --nt;
        int mt = p - nt * (nt + 1) / 2;    // mt <= nt
        int b = bh >> 3, h = bh & 7;

        const bf16* A  = Q  + ((size_t)(b * N_ + nt * 128)) * HDK + h * DK_;
        const bf16* Bp = Kx + ((size_t)(b * N_ + mt * 128)) * HDK + h * DK_;
        bf16* C = sim + (((size_t)(b * H_ + h)) * N_ + nt * 128) * N_ + mt * 128;

        loop_nt(acc, dsm, A, HDK, Bp, HDK, DK_ / 32, tid, wm, wn);
        ep_bf16<1>(acc, dsm, C, N_, nt * 128, mt * 128, tid, wm, wn);
    }
}

// AV split-K partials, BK=64: block = 128-row sim tile x 128 V-cols x 2 heads.
// 3-stage ring (prologue 2, wait 1). A ld = N_, B ld = DV_ (per-head layouts).
__global__ __launch_bounds__(128) void k_avp(const bf16* __restrict__ sim,
                                             const bf16* __restrict__ V,
                                             float* __restrict__ part) {
    int vt = blockIdx.x;
    int tn = 15 - blockIdx.y;            // heavy tiles first
    int z = blockIdx.z;
    int b = z >> 2, s = z & 3;           // split s covers heads {2s, 2s+1}

    extern __shared__ char dsm[];
    uint32_t sb = smem_u32(dsm);
    int tid = threadIdx.x, wid = tid >> 5;
    int wm = wid & 1, wn = wid >> 1;     // warp tile 64x64 over 128x128 output

    const bf16* A0 = sim + (((size_t)(b * H_ + 2 * s)) * N_ + tn * 128) * N_;
    const bf16* A1 = A0 + (size_t)N_ * N_;
    const bf16* V0 = V + ((size_t)(b * H_ + 2 * s)) * N_ * DV_ + vt * 128;
    const bf16* V1 = V0 + (size_t)N_ * DV_;

    const int nkh = (tn + 1) * 2;        // K=64 chunks per head (causal bound), >= 2
    const int nk  = nkh * 2;             // two heads; >= 4

    FragC acc[4][4];
#pragma unroll
    for (int i = 0; i < 4; ++i)
#pragma unroll
        for (int j = 0; j < 4; ++j) wmma::fill_fragment(acc[i][j], 0.0f);

#pragma unroll
    for (int sg = 0; sg < 2; ++sg) {     // prologue chunks all in head 2s (nkh >= 2)
        ld_A72   (sb + sg * AVP_STAGE, A0 + sg * 64, N_, tid);
        ld_Brow64(sb + sg * AVP_STAGE + AVP_A_BYTES,
                  V0 + (size_t)(sg * 64) * DV_, DV_, tid);
        cp_commit();
    }
    for (int i = 0; i < nk; ++i) {
        cp_wait1();
        __syncthreads();
        int ci = i + 2;
        if (ci < nk) {
            int hl = ci / nkh, kc = ci % nkh;
            const bf16* Ah = hl ? A1 : A0;
            const bf16* Vh = hl ? V1 : V0;
            uint32_t st = sb + (uint32_t)(ci % 3) * AVP_STAGE;
            ld_A72   (st, Ah + kc * 64, N_, tid);
            ld_Brow64(st + AVP_A_BYTES, Vh + (size_t)(kc * 64) * DV_, DV_, tid);
        }
        cp_commit();
        const bf16* As = reinterpret_cast<const bf16*>(dsm + (i % 3) * AVP_STAGE);
        mma_w64r64(acc, As, As + AVP_A_BYTES / 2, wm, wn);
    }
    __syncthreads();

    // epilogue: stage 128x136 fp32, plain float4 stores to partial buffer
    float* stg = reinterpret_cast<float*>(dsm);
    stage_acc16(acc, stg, wm, wn);
    __syncthreads();
    float* pb = part + (size_t)s * (B_ * N_ * DV_);
    size_t rowbase = (size_t)(b * N_ + tn * 128);
#pragma unroll
    for (int it = 0; it < 32; ++it) {
        int idx = it * 128 + tid;
        int r = idx >> 5, cv = idx & 31;
        size_t o = (rowbase + r) * (size_t)DV_ + vt * 128 + cv * 4;
        const float* p = stg + r * EP_STRIDE + cv * 4;
        *reinterpret_cast<float4*>(pb + o) = make_float4(p[0], p[1], p[2], p[3]);
    }
}

// final reduce: out = x + sum of 4 partials
__global__ void k_reduce(const float4* __restrict__ x,
                         const float4* __restrict__ part,
                         float4* __restrict__ out) {
    constexpr int NT4 = (B_ * N_ * DV_) / 4;   // 1048576
    int i = blockIdx.x * blockDim.x + threadIdx.x;
    if (i >= NT4) return;
    float4 v = x[i];
#pragma unroll
    for (int s = 0; s < NSPLIT; ++s) {
        float4 p = part[(size_t)s * NT4 + i];
        v.x += p.x; v.y += p.y; v.z += p.z; v.w += p.w;
    }
    out[i] = v;
}

// ---------------- host launcher ---------------------------------------------------
extern "C" void kernel_launch(void* const* d_in, const int* in_sizes, int n_in,
                              void* d_out, int out_size) {
    (void)in_sizes; (void)n_in; (void)out_size;
    const float* x  = (const float*)d_in[0];
    const float* Wq = (const float*)d_in[1];
    const float* Wk = (const float*)d_in[2];
    const float* Wv = (const float*)d_in[3];

    bf16 *xb, *wqb, *wkb, *wvb, *Q, *K, *V, *sim;
    float* part;
    cudaGetSymbolAddress((void**)&xb,  g_xb);
    cudaGetSymbolAddress((void**)&wqb, g_wqb);
    cudaGetSymbolAddress((void**)&wkb, g_wkb);
    cudaGetSymbolAddress((void**)&wvb, g_wvb);
    cudaGetSymbolAddress((void**)&Q,   g_Q);
    cudaGetSymbolAddress((void**)&K,   g_K);
    cudaGetSymbolAddress((void**)&V,   g_V);
    cudaGetSymbolAddress((void**)&sim, g_sim);
    cudaGetSymbolAddress((void**)&part, g_part);

    cudaFuncSetAttribute(k_qk,  cudaFuncAttributeMaxDynamicSharedMemorySize, DSMEM);
    cudaFuncSetAttribute(k_sv,  cudaFuncAttributeMaxDynamicSharedMemorySize, DSMEM);
    cudaFuncSetAttribute(k_avp, cudaFuncAttributeMaxDynamicSharedMemorySize, AVP_DSMEM);

    // one conversion launch for x, Wq, Wk, Wv
    constexpr int TOT4 = (B_ * N_ * D_ + 2 * H_ * DK_ * D_ + H_ * DV_ * D_) / 4;
    conv_all_kernel<<<(TOT4 + 255) / 256, 256>>>(
        reinterpret_cast<const float4*>(x),
        reinterpret_cast<const float4*>(Wq),
        reinterpret_cast<const float4*>(Wk),
        reinterpret_cast<const float4*>(Wv),
        reinterpret_cast<__nv_bfloat162*>(xb),
        reinterpret_cast<__nv_bfloat162*>(wqb),
        reinterpret_cast<__nv_bfloat162*>(wkb),
        reinterpret_cast<__nv_bfloat162*>(wvb));

    // Q and K projections (512 blocks)
    k_qk<<<dim3(16, (B_ * N_) / 128), 128, DSMEM>>>(xb, wqb, wkb, Q, K);

    // merged V-projection + scores: 2048 V blocks + 2176 scores blocks
    k_sv<<<4224, 128, DSMEM>>>(xb, wvb, Q, K, V, sim);

    // AV partials: 8 vt x 16 tn x (2 b x 4 splits) = 1024 blocks, heavy-first, BK=64
    k_avp<<<dim3(8, 16, 8), 128, AVP_DSMEM>>>(sim, V, part);

    // out = x + sum partials
    constexpr int NT4 = (B_ * N_ * DV_) / 4;
    k_reduce<<<(NT4 + 255) / 256, 256>>>(
        reinterpret_cast<const float4*>(x),
        reinterpret_cast<const float4*>(part),
        reinterpret_cast<float4*>(d_out));
}